// round 1
// baseline (speedup 1.0000x reference)
#include <cuda_runtime.h>

// HopfOscillatorModule: B x 32-oscillator CPG step.
// out = [psi_dot | r_d | r_d_dot] per row.
//
// Math restructure (vs reference O(B*N^2) sin calls):
//   sin(pj - pi - phi_ij) expanded =>
//   coupling_i = cos(pi) * P_i + sin(pi) * Qt_i
//   P  = A x - B y,  Qt = -B x - A y
//   A = w_zd cos(phi_zd), B = w_zd sin(phi_zd)   (precomputed once)
//   x_j = r_j sin(p_j),  y_j = r_j cos(p_j)      (one sincos per (row, j))
//
// Two batch rows per thread, packed into f32x2 FMAs (Blackwell packed fp32).

#define NOSC 32
#define TWO_PI 6.283185307179586f

__device__ float4 g_T1[NOSC * NOSC];  // (A, A, -B, -B)
__device__ float2 g_T2[NOSC * NOSC];  // (-A, -A)
__device__ float4 g_par[NOSC];        // (K0, K1, K2, two_pi_v)

__device__ __forceinline__ float sigmoidf_(float x) { return 1.0f / (1.0f + expf(-x)); }

// ---------------- setup: activated params + coupling coefficient tables ---------------
__global__ void hopf_setup_kernel(const float* __restrict__ v, const float* __restrict__ b,
                                  const float* __restrict__ c, const float* __restrict__ w,
                                  const float* __restrict__ phi)
{
    int k = threadIdx.x;  // 0..1023 == flat index into the 32x32 zero-diag matrices
    float A = 0.0f, Bc = 0.0f;
    if (k < 1023) {
        // _zero_diag mapping: z = concat([zeros(31,1), P],1).ravel() ++ [0] -> (32,32)
        int t = k / 33, pos = k % 33;
        if (pos != 0) {
            float wa = sigmoidf_(w[t * 32 + pos - 1]);           // W_MAX = 1
            float pa = TWO_PI * sigmoidf_(phi[t * 32 + pos - 1]);
            float sp, cp;
            sincosf(pa, &sp, &cp);
            A = wa * cp;
            Bc = wa * sp;
        }
    }
    g_T1[k] = make_float4(A, A, -Bc, -Bc);
    g_T2[k] = make_float2(-A, -A);
    if (k < NOSC) {
        float va = 5.0f * sigmoidf_(v[k]);
        float ba = 2.0f * sigmoidf_(b[k]);
        float ca = 10.0f * sigmoidf_(c[k]);
        float K1 = 0.25f * ca * ca;
        // r_d_dot = K0 - K1*r - K2*rd
        g_par[k] = make_float4(K1 * ba, K1, ca, TWO_PI * va);
    }
}

// ---------------- packed f32x2 helpers ----------------
__device__ __forceinline__ unsigned long long pk2(float lo, float hi) {
    unsigned long long r;
    asm("mov.b64 %0, {%1, %2};" : "=l"(r) : "f"(lo), "f"(hi));
    return r;
}
__device__ __forceinline__ void upk2(unsigned long long v, float& lo, float& hi) {
    asm("mov.b64 {%0, %1}, %2;" : "=f"(lo), "=f"(hi) : "l"(v));
}
__device__ __forceinline__ void ffma2(unsigned long long& d, unsigned long long a,
                                      unsigned long long b) {
    asm("fma.rn.f32x2 %0, %1, %2, %0;" : "+l"(d) : "l"(a), "l"(b));
}

// ---------------- main kernel: 2 rows per thread ----------------
__global__ __launch_bounds__(128) void hopf_kernel(const float* __restrict__ in,
                                                   float* __restrict__ out, int nrows)
{
    __shared__ float4 sT1[NOSC * NOSC];
    __shared__ float2 sT2[NOSC * NOSC];
    __shared__ float4 sPar[NOSC];

    int tid = threadIdx.x;
    for (int k = tid; k < NOSC * NOSC; k += 128) {
        sT1[k] = g_T1[k];
        sT2[k] = g_T2[k];
    }
    if (tid < NOSC) sPar[tid] = g_par[tid];
    __syncthreads();

    int t = blockIdx.x * 128 + tid;
    int row0 = 2 * t;
    if (row0 >= nrows) return;

    const float4* in0 = (const float4*)(in + (size_t)row0 * 96);
    const float4* in1 = (const float4*)(in + (size_t)(row0 + 1) * 96);
    float4* out0 = (float4*)(out + (size_t)row0 * 96);
    float4* out1 = (float4*)(out + (size_t)(row0 + 1) * 96);

    unsigned long long X[NOSC], Y[NOSC];  // packed (row0,row1) of r*sin(psi), r*cos(psi)

    // Phase 1: load, sincos, x/y, and emit r_d + r_d_dot thirds of the output.
#pragma unroll
    for (int q = 0; q < 8; q++) {
        float4 p0 = in0[q],      p1 = in1[q];       // psi
        float4 rr0 = in0[8 + q], rr1 = in1[8 + q];  // r
        float4 d0 = in0[16 + q], d1 = in1[16 + q];  // r_d

        float a0[4] = {p0.x, p0.y, p0.z, p0.w};
        float a1[4] = {p1.x, p1.y, p1.z, p1.w};
        float b0[4] = {rr0.x, rr0.y, rr0.z, rr0.w};
        float b1[4] = {rr1.x, rr1.y, rr1.z, rr1.w};
        float e0[4] = {d0.x, d0.y, d0.z, d0.w};
        float e1[4] = {d1.x, d1.y, d1.z, d1.w};
        float f0[4], f1[4];

#pragma unroll
        for (int e = 0; e < 4; e++) {
            float s0, c0, s1, c1;
            __sincosf(a0[e], &s0, &c0);
            __sincosf(a1[e], &s1, &c1);
            X[4 * q + e] = pk2(b0[e] * s0, b1[e] * s1);
            Y[4 * q + e] = pk2(b0[e] * c0, b1[e] * c1);
            float4 par = sPar[4 * q + e];
            f0[e] = fmaf(-par.z, e0[e], fmaf(-par.y, b0[e], par.x));
            f1[e] = fmaf(-par.z, e1[e], fmaf(-par.y, b1[e], par.x));
        }
        out0[8 + q] = d0;   // r_d passthrough
        out1[8 + q] = d1;
        out0[16 + q] = make_float4(f0[0], f0[1], f0[2], f0[3]);  // r_d_dot
        out1[16 + q] = make_float4(f1[0], f1[1], f1[2], f1[3]);
    }

    // Phase 2: coupling matvecs, 4 output oscillators (i) per group.
    const ulonglong2* T1u = reinterpret_cast<const ulonglong2*>(sT1);
    const unsigned long long* T2u = reinterpret_cast<const unsigned long long*>(sT2);

    for (int g = 0; g < 8; g++) {
        unsigned long long P[4] = {0ull, 0ull, 0ull, 0ull};
        unsigned long long Q[4] = {0ull, 0ull, 0ull, 0ull};
        int base = g * 4 * NOSC;

#pragma unroll
        for (int j = 0; j < NOSC; j++) {
            unsigned long long xj = X[j], yj = Y[j];
#pragma unroll
            for (int u = 0; u < 4; u++) {
                ulonglong2 t1 = T1u[base + u * NOSC + j];       // (A,A) | (-B,-B)
                unsigned long long t2 = T2u[base + u * NOSC + j];  // (-A,-A)
                ffma2(P[u], t1.x, xj);   // P += A*x
                ffma2(P[u], t1.y, yj);   // P += -B*y
                ffma2(Q[u], t1.y, xj);   // Qt += -B*x
                ffma2(Q[u], t2, yj);     // Qt += -A*y
            }
        }

        // finalize psi_dot for i = 4g..4g+3 (reload psi, L1-hot)
        float4 ps0 = in0[g], ps1 = in1[g];
        float a0[4] = {ps0.x, ps0.y, ps0.z, ps0.w};
        float a1[4] = {ps1.x, ps1.y, ps1.z, ps1.w};
        float o0v[4], o1v[4];
#pragma unroll
        for (int u = 0; u < 4; u++) {
            float tpv = sPar[4 * g + u].w;
            float s0, c0, s1, c1;
            __sincosf(a0[u], &s0, &c0);
            __sincosf(a1[u], &s1, &c1);
            float plo, phi_, qlo, qhi;
            upk2(P[u], plo, phi_);
            upk2(Q[u], qlo, qhi);
            o0v[u] = tpv + c0 * plo + s0 * qlo;
            o1v[u] = tpv + c1 * phi_ + s1 * qhi;
        }
        out0[g] = make_float4(o0v[0], o0v[1], o0v[2], o0v[3]);
        out1[g] = make_float4(o1v[0], o1v[1], o1v[2], o1v[3]);
    }
}

extern "C" void kernel_launch(void* const* d_in, const int* in_sizes, int n_in,
                              void* d_out, int out_size)
{
    const float* states = (const float*)d_in[0];
    const float* v = (const float*)d_in[1];
    const float* b = (const float*)d_in[2];
    const float* c = (const float*)d_in[3];
    const float* w = (const float*)d_in[4];
    const float* phi = (const float*)d_in[5];
    int nrows = in_sizes[0] / 96;

    hopf_setup_kernel<<<1, 1024>>>(v, b, c, w, phi);

    int nthreads = (nrows + 1) / 2;
    int blocks = (nthreads + 127) / 128;
    hopf_kernel<<<blocks, 128>>>(states, (float*)d_out, nrows);
}

// round 2
// speedup vs baseline: 1.1803x; 1.1803x over previous
#include <cuda_runtime.h>

// HopfOscillatorModule, round 2: lane = oscillator, warp = packed row-pair.
//
//   coupling_i = cos(psi_i)*(P1-P2) - sin(psi_i)*(Q1+Q2)
//   P1 = sum_j A_ij x_j, P2 = sum_j B_ij y_j, Q1 = sum_j B_ij x_j, Q2 = sum_j A_ij y_j
//   A = w_zd cos(phi_zd), B = w_zd sin(phi_zd), x_j = r_j sin(psi_j), y_j = r_j cos(psi_j)
//
// Two batch rows packed per lane via fma.rn.f32x2. Coefficients in registers
// (64/lane), x/y broadcast per-j via one LDS.128 from a per-warp shared buffer.

#define NOSC 32
#define TWO_PI 6.283185307179586f
#define CTA_THREADS 128
#define NUM_CTAS 1024

__device__ float g_A[NOSC * NOSC];   // w*cos(phi), zero-diag, [i][j]
__device__ float g_B[NOSC * NOSC];   // w*sin(phi), zero-diag, [i][j]
__device__ float4 g_par[NOSC];       // (K0, K1, K2, two_pi_v)

__device__ __forceinline__ float sigmoidf_(float x) { return 1.0f / (1.0f + expf(-x)); }

__global__ void hopf_setup_kernel(const float* __restrict__ v, const float* __restrict__ b,
                                  const float* __restrict__ c, const float* __restrict__ w,
                                  const float* __restrict__ phi)
{
    int k = threadIdx.x;  // flat index into 32x32 zero-diag matrices
    float A = 0.0f, Bc = 0.0f;
    if (k < 1023) {
        // _zero_diag: z = concat([zeros(31,1), P],1).ravel() ++ [0] -> (32,32)
        int t = k / 33, pos = k % 33;
        if (pos != 0) {
            float wa = sigmoidf_(w[t * 32 + pos - 1]);            // W_MAX = 1
            float pa = TWO_PI * sigmoidf_(phi[t * 32 + pos - 1]);
            float sp, cp;
            sincosf(pa, &sp, &cp);
            A = wa * cp;
            Bc = wa * sp;
        }
    }
    g_A[k] = A;
    g_B[k] = Bc;
    if (k < NOSC) {
        float va = 5.0f * sigmoidf_(v[k]);
        float ba = 2.0f * sigmoidf_(b[k]);
        float ca = 10.0f * sigmoidf_(c[k]);
        float K1 = 0.25f * ca * ca;
        g_par[k] = make_float4(K1 * ba, K1, ca, TWO_PI * va);  // r_d_dot = K0 - K1*r - K2*rd
    }
}

// ---------------- packed f32x2 helpers ----------------
typedef unsigned long long u64;
__device__ __forceinline__ u64 pk2(float lo, float hi) {
    u64 r;
    asm("mov.b64 %0, {%1, %2};" : "=l"(r) : "f"(lo), "f"(hi));
    return r;
}
__device__ __forceinline__ u64 dup2(float a) {
    u64 r;
    asm("mov.b64 %0, {%1, %1};" : "=l"(r) : "f"(a));
    return r;
}
__device__ __forceinline__ void upk2(u64 v, float& lo, float& hi) {
    asm("mov.b64 {%0, %1}, %2;" : "=f"(lo), "=f"(hi) : "l"(v));
}
__device__ __forceinline__ void ffma2(u64& d, u64 a, u64 b) {
    asm("fma.rn.f32x2 %0, %1, %2, %0;" : "+l"(d) : "l"(a), "l"(b));
}
__device__ __forceinline__ u64 sub2(u64 a, u64 b) {
    u64 r;
    asm("sub.rn.f32x2 %0, %1, %2;" : "=l"(r) : "l"(a), "l"(b));
    return r;
}
__device__ __forceinline__ u64 add2(u64 a, u64 b) {
    u64 r;
    asm("add.rn.f32x2 %0, %1, %2;" : "=l"(r) : "l"(a), "l"(b));
    return r;
}

__global__ __launch_bounds__(CTA_THREADS) void hopf_kernel(const float* __restrict__ in,
                                                           float* __restrict__ out,
                                                           int nrows, int nwarps_total)
{
    __shared__ float sA[NOSC * 33];        // padded stride 33: conflict-free row reads
    __shared__ float sB[NOSC * 33];
    __shared__ ulonglong2 sXY[CTA_THREADS / 32][NOSC];  // per-warp (x,y) packed

    int tid = threadIdx.x;
    // Stage coefficient matrices coalesced into padded shared.
    for (int k = tid; k < NOSC * NOSC; k += CTA_THREADS) {
        int i = k >> 5, j = k & 31;
        sA[i * 33 + j] = g_A[k];
        sB[i * 33 + j] = g_B[k];
    }
    __syncthreads();

    int lane = tid & 31;
    int wid = tid >> 5;

    // Per-lane coefficient row -> registers (64 regs). Bank = (lane+j)%32: conflict-free.
    float Ac[NOSC], Bc[NOSC];
#pragma unroll
    for (int j = 0; j < NOSC; j++) {
        Ac[j] = sA[lane * 33 + j];
        Bc[j] = sB[lane * 33 + j];
    }
    float4 par = g_par[lane];  // (K0, K1, K2, two_pi_v)

    int npairs = (nrows + 1) >> 1;
    int gw = blockIdx.x * (CTA_THREADS / 32) + wid;

    for (int p = gw; p < npairs; p += nwarps_total) {
        int row0 = 2 * p;
        bool has1 = (row0 + 1) < nrows;
        const float* r0p = in + (size_t)row0 * 96;
        const float* r1p = has1 ? (r0p + 96) : r0p;

        // Coalesced loads: each segment is a 128B line.
        float psi0 = r0p[lane], psi1 = r1p[lane];
        float rr0 = r0p[32 + lane], rr1 = r1p[32 + lane];
        float rd0 = r0p[64 + lane], rd1 = r1p[64 + lane];

        float s0, c0, s1, c1;
        __sincosf(psi0, &s0, &c0);
        __sincosf(psi1, &s1, &c1);

        ulonglong2 xy;
        xy.x = pk2(rr0 * s0, rr1 * s1);  // x = r*sin(psi), packed (row0,row1)
        xy.y = pk2(rr0 * c0, rr1 * c1);  // y = r*cos(psi)
        sXY[wid][lane] = xy;
        __syncwarp();

        u64 P1 = 0ull, P2 = 0ull, Q1 = 0ull, Q2 = 0ull;
#pragma unroll
        for (int j = 0; j < NOSC; j++) {
            ulonglong2 vj = sXY[wid][j];   // LDS.128 broadcast
            u64 a2 = dup2(Ac[j]);
            u64 b2 = dup2(Bc[j]);
            ffma2(P1, a2, vj.x);
            ffma2(P2, b2, vj.y);
            ffma2(Q1, b2, vj.x);
            ffma2(Q2, a2, vj.y);
        }
        __syncwarp();  // protect sXY before next iteration's store

        u64 P = sub2(P1, P2);
        u64 Q = add2(Q1, Q2);
        float pl, ph, ql, qh;
        upk2(P, pl, ph);
        upk2(Q, ql, qh);

        float psidot0 = fmaf(c0, pl, fmaf(-s0, ql, par.w));
        float psidot1 = fmaf(c1, ph, fmaf(-s1, qh, par.w));
        float f0 = fmaf(-par.z, rd0, fmaf(-par.y, rr0, par.x));
        float f1 = fmaf(-par.z, rd1, fmaf(-par.y, rr1, par.x));

        float* o0 = out + (size_t)row0 * 96;
        o0[lane] = psidot0;
        o0[32 + lane] = rd0;
        o0[64 + lane] = f0;
        if (has1) {
            float* o1 = o0 + 96;
            o1[lane] = psidot1;
            o1[32 + lane] = rd1;
            o1[64 + lane] = f1;
        }
    }
}

extern "C" void kernel_launch(void* const* d_in, const int* in_sizes, int n_in,
                              void* d_out, int out_size)
{
    const float* states = (const float*)d_in[0];
    const float* v = (const float*)d_in[1];
    const float* b = (const float*)d_in[2];
    const float* c = (const float*)d_in[3];
    const float* w = (const float*)d_in[4];
    const float* phi = (const float*)d_in[5];
    int nrows = in_sizes[0] / 96;

    hopf_setup_kernel<<<1, 1024>>>(v, b, c, w, phi);

    int nwarps_total = NUM_CTAS * (CTA_THREADS / 32);
    hopf_kernel<<<NUM_CTAS, CTA_THREADS>>>(states, (float*)d_out, nrows, nwarps_total);
}